// round 7
// baseline (speedup 1.0000x reference)
#include <cuda_runtime.h>
#include <cstdint>

// Problem constants (N=2, C=32, H=64, W=128, D=48 fixed by dataset shape)
#define N_   2
#define C_   32
#define H_   64
#define W_   128
#define D_   48
#define WC_  (W_ + D_)           // 176
#define V8PR (WC_ / 8)           // 22 float8 per output row
#define DSTRIDE8 (H_ * V8PR)     // float8 stride between d slices: 1408
#define DCHUNK 16                // d-slices per thread (3 chunks)
#define TPB   128

// 256-bit streaming store (sm_100+)
__device__ __forceinline__ void stcs_v8(float* p, const float v[8])
{
    asm volatile(
        "st.global.cs.v8.f32 [%0], {%1,%2,%3,%4,%5,%6,%7,%8};"
        :: "l"(p),
           "f"(v[0]), "f"(v[1]), "f"(v[2]), "f"(v[3]),
           "f"(v[4]), "f"(v[5]), "f"(v[6]), "f"(v[7])
        : "memory");
}

// out[n][c2][d][h][j]  (j in [0,176)), i = 47-d:
//   c2 <  32: out = x[n,c2,h,j]      if i <= j < 128   else 0
//   c2 >= 32: out = y[n,c2-32,h,j-i] if 0 <= j-i < 128 else 0
// One thread owns (n, c2, h, j8) and emits DCHUNK d-slices of one float8.
__global__ void __launch_bounds__(TPB)
cost_volume_kernel(const float* __restrict__ x,
                   const float* __restrict__ y,
                   float* __restrict__ out)
{
    const int tid = blockIdx.x * blockDim.x + threadIdx.x;
    const int d0  = blockIdx.y * DCHUNK;   // 0, 16, 32

    // tid = rowbase * 22 + j8,  rowbase = (n*64 + c2)*64 + h
    const int j8      = tid % V8PR;
    const int rowbase = tid / V8PR;

    const int h   = rowbase & 63;
    const int c2h = rowbase >> 6;
    const int c2  = c2h & 63;
    const int n   = c2h >> 6;

    const int j0 = j8 * 8;

    // output pointer (float) at d = d0
    float* o = out + (((size_t)(n * 64 + c2) * (D_ * H_) + (size_t)d0 * H_ + h) * V8PR + j8) * 8;

    if (c2 < C_) {
        // ---------------- x branch ----------------
        const int t0 = (D_ - 1) - j0;   // lane0 valid when d >= t0; lane k when d >= t0-k

        if (j0 >= W_ || d0 + (DCHUNK - 1) < t0 - 7) {
            // entirely outside x width (j8 >= 16), or window closed for the whole chunk
            const float z[8] = {0.f, 0.f, 0.f, 0.f, 0.f, 0.f, 0.f, 0.f};
            #pragma unroll
            for (int dd = 0; dd < DCHUNK; ++dd) { stcs_v8(o, z); o += DSTRIDE8 * 8; }
            return;
        }

        const float* src = x + (((size_t)n * C_ + c2) * H_ + h) * W_ + j0;
        float v[8];
        {
            float4 a = *reinterpret_cast<const float4*>(src);
            float4 b = *reinterpret_cast<const float4*>(src + 4);
            v[0] = a.x; v[1] = a.y; v[2] = a.z; v[3] = a.w;
            v[4] = b.x; v[5] = b.y; v[6] = b.z; v[7] = b.w;
        }

        if (d0 >= t0) {
            // fully open for whole chunk: replicated stores
            #pragma unroll
            for (int dd = 0; dd < DCHUNK; ++dd) { stcs_v8(o, v); o += DSTRIDE8 * 8; }
        } else {
            #pragma unroll
            for (int dd = 0; dd < DCHUNK; ++dd) {
                const int d = d0 + dd;
                float w[8];
                #pragma unroll
                for (int k = 0; k < 8; ++k)
                    w[k] = (d >= t0 - k) ? v[k] : 0.f;
                stcs_v8(o, w);
                o += DSTRIDE8 * 8;
            }
        }
    } else {
        // ---------------- y branch ----------------
        // source lane k at slice d: s = j0 + k - 47 + d
        const float* row = y + (((size_t)n * C_ + (c2 - C_)) * H_ + h) * W_;

        float cur[8];
        #pragma unroll
        for (int k = 0; k < 8; ++k) {
            int s = j0 + k - (D_ - 1) + d0;
            cur[k] = ((unsigned)s < (unsigned)W_) ? __ldg(row + s) : 0.f;
        }

        #pragma unroll
        for (int dd = 0; dd < DCHUNK; ++dd) {
            stcs_v8(o, cur);
            o += DSTRIDE8 * 8;
            // refill lane 7 for slice d0+dd+1: s = j0 + 7 - 47 + (d0+dd+1) = j0 + d0 + dd - 39
            #pragma unroll
            for (int k = 0; k < 7; ++k) cur[k] = cur[k + 1];
            int s = j0 + d0 + dd - (D_ - 1 - 8);   // = j0 + d0 + dd - 39
            cur[7] = ((unsigned)s < (unsigned)W_) ? __ldg(row + s) : 0.f;
        }
    }
}

extern "C" void kernel_launch(void* const* d_in, const int* in_sizes, int n_in,
                              void* d_out, int out_size)
{
    const float* x = (const float*)d_in[0];
    const float* y = (const float*)d_in[1];

    // threads = N * 2C * H * V8PR = 2*64*64*22 = 180224 (divisible by 128)
    const int total_threads = N_ * 2 * C_ * H_ * V8PR;
    dim3 grid(total_threads / TPB, D_ / DCHUNK, 1);

    cost_volume_kernel<<<grid, TPB>>>(x, y, (float*)d_out);
}

// round 8
// speedup vs baseline: 1.2039x; 1.2039x over previous
#include <cuda_runtime.h>
#include <cstdint>

// Problem constants (N=2, C=32, H=64, W=128, D=48 fixed by dataset shape)
#define N_   2
#define C_   32
#define H_   64
#define W_   128
#define D_   48
#define WC_  (W_ + D_)           // 176
#define VPR  (WC_ / 4)           // 44 float4 per output row
#define DSTRIDE (H_ * VPR)       // float4 stride between consecutive d slices: 2816
#define DCHUNK 8                 // d-slices per thread (6 chunks total)
#define TPB   256

// out[n][c2][d][h][j]  (j in [0,176)), i = 47-d:
//   c2 <  32: out = x[n,c2,h,j]      if i <= j < 128   else 0
//   c2 >= 32: out = y[n,c2-32,h,j-i] if 0 <= j-i < 128 else 0
__global__ void __launch_bounds__(TPB)
cost_volume_kernel(const float* __restrict__ x,
                   const float* __restrict__ y,
                   float4* __restrict__ out)
{
    const int tid = blockIdx.x * blockDim.x + threadIdx.x;
    const int d0  = blockIdx.y * DCHUNK;   // 0, 8, 16, 24, 32, 40

    // tid = rowbase * 44 + j4,  rowbase = (n*64 + c2)*64 + h
    const int j4      = tid % VPR;
    const int rowbase = tid / VPR;

    const int h   = rowbase & 63;
    const int c2h = rowbase >> 6;
    const int c2  = c2h & 63;
    const int n   = c2h >> 6;

    const int j0 = j4 * 4;

    // out float4 index at d=d0
    float4* o = out + ((size_t)(n * 64 + c2) * (D_ * H_) + (size_t)d0 * H_ + h) * VPR + j4;

    if (c2 < C_) {
        // ---------------- x branch ----------------
        const int t0 = (D_ - 1) - j0;   // lane0 valid when d >= t0

        if (j0 >= W_ || d0 + (DCHUNK - 1) < t0 - 3) {
            // fully outside x width, or window closed for all lanes this chunk
            const float4 z = make_float4(0.f, 0.f, 0.f, 0.f);
            #pragma unroll
            for (int dd = 0; dd < DCHUNK; ++dd) { __stcs(o, z); o += DSTRIDE; }
            return;
        }

        const float4 v =
            *reinterpret_cast<const float4*>(x + (((size_t)n * C_ + c2) * H_ + h) * W_ + j0);

        if (d0 >= t0) {
            // window fully open for the whole chunk: pure replicated stores
            #pragma unroll
            for (int dd = 0; dd < DCHUNK; ++dd) { __stcs(o, v); o += DSTRIDE; }
        } else {
            #pragma unroll
            for (int dd = 0; dd < DCHUNK; ++dd) {
                const int d = d0 + dd;
                float4 w;
                w.x = (d >= t0    ) ? v.x : 0.f;
                w.y = (d >= t0 - 1) ? v.y : 0.f;
                w.z = (d >= t0 - 2) ? v.z : 0.f;
                w.w = (d >= t0 - 3) ? v.w : 0.f;
                __stcs(o, w);
                o += DSTRIDE;
            }
        }
    } else {
        // ---------------- y branch ----------------
        // source lane k at slice d: s = j0 + k - 47 + d
        const float* row = y + (((size_t)n * C_ + (c2 - C_)) * H_ + h) * W_;

        float cur[4];
        #pragma unroll
        for (int k = 0; k < 4; ++k) {
            int s = j0 + k - (D_ - 1) + d0;
            cur[k] = ((unsigned)s < (unsigned)W_) ? __ldg(row + s) : 0.f;
        }

        #pragma unroll
        for (int dd = 0; dd < DCHUNK; ++dd) {
            __stcs(o, make_float4(cur[0], cur[1], cur[2], cur[3]));
            o += DSTRIDE;
            // refill lane 3 for slice d0+dd+1: s = j0 + 3 - 47 + (d0+dd+1) = j0 + d0 + dd - 43
            cur[0] = cur[1];
            cur[1] = cur[2];
            cur[2] = cur[3];
            int s = j0 + d0 + dd - (D_ - 1 - 4);
            cur[3] = ((unsigned)s < (unsigned)W_) ? __ldg(row + s) : 0.f;
        }
    }
}

extern "C" void kernel_launch(void* const* d_in, const int* in_sizes, int n_in,
                              void* d_out, int out_size)
{
    const float* x = (const float*)d_in[0];
    const float* y = (const float*)d_in[1];

    // grid.x covers (n, c2, h, j4) = 2*64*64*44 = 360448 threads; grid.y = 6 d-chunks
    const int total_threads = N_ * 2 * C_ * H_ * VPR;   // divisible by 256
    dim3 grid(total_threads / TPB, D_ / DCHUNK, 1);

    cost_volume_kernel<<<grid, TPB>>>(x, y, (float4*)d_out);
}